// round 16
// baseline (speedup 1.0000x reference)
#include <cuda_runtime.h>
#include <stdint.h>

// Static scratch (no device allocs allowed). __device__ globals are
// zero-initialized at module load; aggregate_kernel re-zeroes g_cursor after
// reading so every graph replay starts clean without a zeroing pass.
#define MAX_NODES 131072
#define BUCKET_CAP 64
#define MAX_SPILL 8192

__device__ int g_cursor[MAX_NODES];                 // per-node fill cursor == in-degree
__device__ int g_bucket[MAX_NODES * BUCKET_CAP];    // src ids, 64 slots per node
__device__ int g_spill_src[MAX_SPILL];
__device__ int g_spill_dst[MAX_SPILL];
__device__ int g_spill_n;
__device__ int g_is64;                              // edge index dtype flag

// ---------------------------------------------------------------------------
// Kernel 1 (1 block): sniff edge-index dtype + reset spill counter.
// int64 values < 2^31 have zero odd int32 words; int32 node ids are ~uniform
// in [0,1e5): P(128 odd words all zero | int32) ~ 1e-640.
// ---------------------------------------------------------------------------
__global__ void init_kernel(const int* __restrict__ ei32, long long n_words) {
    __shared__ int nz;
    if (threadIdx.x == 0) { nz = 0; g_spill_n = 0; }
    __syncthreads();
    long long limit = n_words < 256 ? n_words : 256;
    long long j = threadIdx.x;            // one word per thread
    if (j < limit && (j & 1) && ei32[j] != 0) atomicOr(&nz, 1);
    __syncthreads();
    if (threadIdx.x == 0) g_is64 = (nz == 0) ? 1 : 0;
}

// ---------------------------------------------------------------------------
// Kernel 2: edge pass — scatter src ids into fixed-capacity buckets.
// 4 edges per thread: vectorized index loads, 4 independent ATOMG->store
// chains in flight per thread (hides the ~318cyc atomic latency).
// Overflow (vanishingly rare, P~1e-18/node) goes to the spill list.
// ---------------------------------------------------------------------------
__global__ void fill_kernel(const void* __restrict__ ei_raw, long long E) {
    long long t = (long long)blockIdx.x * blockDim.x + threadIdx.x;
    long long e0 = t * 4;
    if (e0 >= E) return;

    int s[4], d[4];
    int n = (E - e0 >= 4) ? 4 : (int)(E - e0);

    if (g_is64) {
        const long long* ei = (const long long*)ei_raw;
        if (n == 4) {
            longlong2 sa = *(const longlong2*)(ei + e0);
            longlong2 sb = *(const longlong2*)(ei + e0 + 2);
            longlong2 da = *(const longlong2*)(ei + E + e0);
            longlong2 db = *(const longlong2*)(ei + E + e0 + 2);
            s[0] = (int)sa.x; s[1] = (int)sa.y; s[2] = (int)sb.x; s[3] = (int)sb.y;
            d[0] = (int)da.x; d[1] = (int)da.y; d[2] = (int)db.x; d[3] = (int)db.y;
        } else {
            for (int u = 0; u < n; u++) {
                s[u] = (int)ei[e0 + u];
                d[u] = (int)ei[E + e0 + u];
            }
        }
    } else {
        const int* ei = (const int*)ei_raw;
        if (n == 4) {
            int4 sv = *(const int4*)(ei + e0);
            int4 dv = *(const int4*)(ei + E + e0);
            s[0] = sv.x; s[1] = sv.y; s[2] = sv.z; s[3] = sv.w;
            d[0] = dv.x; d[1] = dv.y; d[2] = dv.z; d[3] = dv.w;
        } else {
            for (int u = 0; u < n; u++) {
                s[u] = ei[e0 + u];
                d[u] = ei[E + e0 + u];
            }
        }
    }

    int pos[4];
    #pragma unroll
    for (int u = 0; u < 4; u++)
        if (u < n) pos[u] = atomicAdd(&g_cursor[d[u]], 1);

    #pragma unroll
    for (int u = 0; u < 4; u++) {
        if (u >= n) break;
        if (pos[u] < BUCKET_CAP) {
            g_bucket[(long long)d[u] * BUCKET_CAP + pos[u]] = s[u];
        } else {
            int sp = atomicAdd(&g_spill_n, 1);
            if (sp < MAX_SPILL) { g_spill_src[sp] = s[u]; g_spill_dst[sp] = d[u]; }
        }
    }
}

// ---------------------------------------------------------------------------
// Kernel 3: aggregate (+ fused spill fixup, + cursor self-reset).
// One warp per dest node. Half-warp float4 layout: lanes 0-15 and 16-31 each
// gather a FULL 256B feature row (16 x float4) for two different srcs in
// parallel. Per 8 srcs: 2 broadcast int4 index loads + 4 LDG.128 gathers.
//   out[d] = feat[d] + (sum_src feat[src] + deg*feat[d]) / max(deg,1)
// ---------------------------------------------------------------------------
__global__ void aggregate_kernel(const float* __restrict__ feat,
                                 float* __restrict__ out,
                                 int n_nodes) {
    int warp = (blockIdx.x * blockDim.x + threadIdx.x) >> 5;
    int lane = threadIdx.x & 31;
    if (warp >= n_nodes) return;

    int half  = lane >> 4;      // 0 or 1: which src of the pair
    int qlane = lane & 15;      // feature chunk (float4) index

    int v   = warp;
    int deg = g_cursor[v];
    if (lane == 0) g_cursor[v] = 0;   // self-clean for the next graph replay
    int cnt = min(deg, BUCKET_CAP);
    const int* bucket = g_bucket + (long long)v * BUCKET_CAP;
    const float4* f4 = (const float4*)feat;

    float4 acc = make_float4(0.0f, 0.0f, 0.0f, 0.0f);

    int k = 0;
    // 8 srcs per iter: 2 broadcast int4 idx loads + 4 gather LDG.128s.
    for (; k + 8 <= cnt; k += 8) {
        int4 ia = *(const int4*)(bucket + k);
        int4 ib = *(const int4*)(bucket + k + 4);
        int s0 = half ? ia.y : ia.x;
        int s1 = half ? ia.w : ia.z;
        int s2 = half ? ib.y : ib.x;
        int s3 = half ? ib.w : ib.z;
        float4 x0 = __ldg(&f4[(long long)s0 * 16 + qlane]);
        float4 x1 = __ldg(&f4[(long long)s1 * 16 + qlane]);
        float4 x2 = __ldg(&f4[(long long)s2 * 16 + qlane]);
        float4 x3 = __ldg(&f4[(long long)s3 * 16 + qlane]);
        acc.x += x0.x + x1.x + x2.x + x3.x;
        acc.y += x0.y + x1.y + x2.y + x3.y;
        acc.z += x0.z + x1.z + x2.z + x3.z;
        acc.w += x0.w + x1.w + x2.w + x3.w;
    }
    // pair tail
    for (; k + 2 <= cnt; k += 2) {
        int2 id = *(const int2*)(bucket + k);
        int s = half ? id.y : id.x;
        float4 x = __ldg(&f4[(long long)s * 16 + qlane]);
        acc.x += x.x; acc.y += x.y; acc.z += x.z; acc.w += x.w;
    }
    // single tail: only half 0 adds it
    if (k < cnt && half == 0) {
        int s = bucket[k];
        float4 x = __ldg(&f4[(long long)s * 16 + qlane]);
        acc.x += x.x; acc.y += x.y; acc.z += x.z; acc.w += x.w;
    }

    // Fused spill fixup (normally g_spill_n == 0): add on half 0 only.
    int spn = g_spill_n;
    if (spn > 0) {
        if (spn > MAX_SPILL) spn = MAX_SPILL;
        for (int i = 0; i < spn; i++) {
            if (g_spill_dst[i] == v && half == 0) {
                float4 x = __ldg(&f4[(long long)g_spill_src[i] * 16 + qlane]);
                acc.x += x.x; acc.y += x.y; acc.z += x.z; acc.w += x.w;
            }
        }
    }

    // Merge the two half-warp partial sums.
    acc.x += __shfl_xor_sync(0xFFFFFFFFu, acc.x, 16);
    acc.y += __shfl_xor_sync(0xFFFFFFFFu, acc.y, 16);
    acc.z += __shfl_xor_sync(0xFFFFFFFFu, acc.z, 16);
    acc.w += __shfl_xor_sync(0xFFFFFFFFu, acc.w, 16);

    if (half == 0) {
        float4 fd = __ldg(&f4[(long long)v * 16 + qlane]);
        float fc  = (float)deg;
        float inv = 1.0f / (float)max(deg, 1);
        float4 r;
        r.x = fd.x + (acc.x + fc * fd.x) * inv;
        r.y = fd.y + (acc.y + fc * fd.y) * inv;
        r.z = fd.z + (acc.z + fc * fd.z) * inv;
        r.w = fd.w + (acc.w + fc * fd.w) * inv;
        ((float4*)out)[(long long)v * 16 + qlane] = r;
    }
}

extern "C" void kernel_launch(void* const* d_in, const int* in_sizes, int n_in,
                              void* d_out, int out_size) {
    const float* feat = (const float*)d_in[0];
    const void* ei = d_in[1];
    float* out = (float*)d_out;

    int n_nodes = in_sizes[0] / 64;            // 100000
    long long E = (long long)in_sizes[1] / 2;  // 1600000

    init_kernel<<<1, 256>>>((const int*)ei, 2 * E);

    {
        long long nthreads = (E + 3) / 4;      // 4 edges per thread
        int threads = 256;
        long long blocks = (nthreads + threads - 1) / threads;
        fill_kernel<<<(unsigned int)blocks, threads>>>(ei, E);
    }

    {
        long long total = (long long)n_nodes * 32;   // one warp per node
        int threads = 256;
        long long blocks = (total + threads - 1) / threads;
        aggregate_kernel<<<(unsigned int)blocks, threads>>>(feat, out, n_nodes);
    }
}